// round 13
// baseline (speedup 1.0000x reference)
#include <cuda_runtime.h>
#include <cuda_fp16.h>
#include <cuda_bf16.h>

// pri scratch: [t_global (1152)][b (64)][n*16+d (512)] fp16 = 75.5 MB
static __device__ __half g_pri[37748736];

// ---------------------------------------------------------------------------
// Kernel 1: pri = x_t @ W_t via bf16 split MMA. Grid 2304: CTA = (t, nd-half).
// 108KB smem, 2 CTAs/SM -> staging (DRAM) overlaps MMA (tensor).
// ---------------------------------------------------------------------------
#define SA 72
#define SB 72
#define SC 264
#define K_PRI_SMEM 110592

__device__ __forceinline__ void mma16816(float* c, const unsigned* a,
                                         unsigned b0, unsigned b1) {
    asm volatile(
        "mma.sync.aligned.m16n8k16.row.col.f32.bf16.bf16.f32 "
        "{%0,%1,%2,%3}, {%4,%5,%6,%7}, {%8,%9}, {%0,%1,%2,%3};"
        : "+f"(c[0]), "+f"(c[1]), "+f"(c[2]), "+f"(c[3])
        : "r"(a[0]), "r"(a[1]), "r"(a[2]), "r"(a[3]), "r"(b0), "r"(b1));
}

__global__ __launch_bounds__(512, 2) void k_pri(
    const float* __restrict__ xT, const float* __restrict__ xA,
    const float* __restrict__ xV, const float* __restrict__ xF,
    const float* __restrict__ wT, const float* __restrict__ wA,
    const float* __restrict__ wV, const float* __restrict__ wF)
{
    extern __shared__ __nv_bfloat16 sm[];
    __nv_bfloat16* Ah = sm;                     // 64 x SA
    __nv_bfloat16* Al = Ah + 64 * SA;
    __nv_bfloat16* Bh = Al + 64 * SA;           // 256 x SB (nd half)
    __nv_bfloat16* Bl = Bh + 256 * SB;
    __half* Cs = reinterpret_cast<__half*>(Bh); // reused after MMA (64 x SC)

    int bid  = blockIdx.x;
    int tg   = bid >> 1;
    int half = bid & 1;
    const float* x; const float* w; int T, t;
    if (tg < 128)      { x = xT; w = wT; T = 128; t = tg;       }
    else if (tg < 640) { x = xA; w = wA; T = 512; t = tg - 128; }
    else if (tg < 896) { x = xV; w = wV; T = 256; t = tg - 640; }
    else               { x = xF; w = wF; T = 256; t = tg - 896; }

    int tid = threadIdx.x;

    // ---- stage x_t -> Ah/Al [b][j] ----
    #pragma unroll
    for (int u = tid; u < 2048; u += 512) {
        int bb = u >> 5, jp = u & 31;
        float2 v2 = *reinterpret_cast<const float2*>(
            x + ((size_t)bb * T + t) * 64 + jp * 2);
        __nv_bfloat16 h0 = __float2bfloat16_rn(v2.x);
        __nv_bfloat16 h1 = __float2bfloat16_rn(v2.y);
        __nv_bfloat162 hh; hh.x = h0; hh.y = h1;
        __nv_bfloat162 ll;
        ll.x = __float2bfloat16_rn(v2.x - __bfloat162float(h0));
        ll.y = __float2bfloat16_rn(v2.y - __bfloat162float(h1));
        *reinterpret_cast<__nv_bfloat162*>(&Ah[bb * SA + jp * 2]) = hh;
        *reinterpret_cast<__nv_bfloat162*>(&Al[bb * SA + jp * 2]) = ll;
    }

    // ---- stage this CTA's half of W_t -> Bh/Bl [nd_local][j] ----
    const float4* w4 = reinterpret_cast<const float4*>(w + (size_t)t * 32768);
    #pragma unroll
    for (int u = tid; u < 2048; u += 512) {
        int d0c = u & 3;            // d-quad
        int jp  = (u >> 2) & 31;    // j-pair
        int nl  = u >> 7;           // local n 0..15
        int nbase = (half * 16 + nl) * 256 + jp * 8 + d0c;
        float4 va = __ldg(w4 + nbase);        // j = 2jp
        float4 vb = __ldg(w4 + nbase + 4);    // j = 2jp+1
        float aa[4] = {va.x, va.y, va.z, va.w};
        float bb[4] = {vb.x, vb.y, vb.z, vb.w};
        #pragma unroll
        for (int q = 0; q < 4; q++) {
            int row = (nl << 4) + d0c * 4 + q;      // local nd 0..255
            __nv_bfloat16 ha = __float2bfloat16_rn(aa[q]);
            __nv_bfloat16 hb = __float2bfloat16_rn(bb[q]);
            __nv_bfloat162 hh; hh.x = ha; hh.y = hb;
            __nv_bfloat162 ll;
            ll.x = __float2bfloat16_rn(aa[q] - __bfloat162float(ha));
            ll.y = __float2bfloat16_rn(bb[q] - __bfloat162float(hb));
            *reinterpret_cast<__nv_bfloat162*>(&Bh[row * SB + jp * 2]) = hh;
            *reinterpret_cast<__nv_bfloat162*>(&Bl[row * SB + jp * 2]) = ll;
        }
    }
    __syncthreads();

    // ---- MMA: warp = (m-half) x (32-nd group) ----
    int lane = tid & 31, wrp = tid >> 5;
    int g  = lane >> 2;
    int tq = lane & 3;
    int mbase  = (wrp & 1) * 32;
    int ndbase = (wrp >> 1) * 32;      // local nd

    float acc[2][4][4];
    #pragma unroll
    for (int mt = 0; mt < 2; mt++)
        #pragma unroll
        for (int nt = 0; nt < 4; nt++)
            #pragma unroll
            for (int q = 0; q < 4; q++) acc[mt][nt][q] = 0.f;

    #pragma unroll
    for (int k0 = 0; k0 < 64; k0 += 16) {
        unsigned ah[2][4], al[2][4];
        #pragma unroll
        for (int mt = 0; mt < 2; mt++) {
            int r0 = mbase + mt * 16 + g;
            int kc = k0 + tq * 2;
            ah[mt][0] = *(const unsigned*)&Ah[r0 * SA + kc];
            ah[mt][1] = *(const unsigned*)&Ah[(r0 + 8) * SA + kc];
            ah[mt][2] = *(const unsigned*)&Ah[r0 * SA + kc + 8];
            ah[mt][3] = *(const unsigned*)&Ah[(r0 + 8) * SA + kc + 8];
            al[mt][0] = *(const unsigned*)&Al[r0 * SA + kc];
            al[mt][1] = *(const unsigned*)&Al[(r0 + 8) * SA + kc];
            al[mt][2] = *(const unsigned*)&Al[r0 * SA + kc + 8];
            al[mt][3] = *(const unsigned*)&Al[(r0 + 8) * SA + kc + 8];
        }
        #pragma unroll
        for (int nt = 0; nt < 4; nt++) {
            int col = ndbase + nt * 8 + g;
            int kc  = k0 + tq * 2;
            unsigned bh0 = *(const unsigned*)&Bh[col * SB + kc];
            unsigned bh1 = *(const unsigned*)&Bh[col * SB + kc + 8];
            unsigned bl0 = *(const unsigned*)&Bl[col * SB + kc];
            unsigned bl1 = *(const unsigned*)&Bl[col * SB + kc + 8];
            #pragma unroll
            for (int mt = 0; mt < 2; mt++) {
                mma16816(acc[mt][nt], ah[mt], bh0, bh1);
                mma16816(acc[mt][nt], ah[mt], bl0, bl1);
                mma16816(acc[mt][nt], al[mt], bh0, bh1);
            }
        }
    }
    __syncthreads();   // B smem no longer needed; reuse as Cs

    #pragma unroll
    for (int mt = 0; mt < 2; mt++)
        #pragma unroll
        for (int nt = 0; nt < 4; nt++) {
            int r0 = mbase + mt * 16 + g;
            int c0 = ndbase + nt * 8 + tq * 2;
            __half2 lo = __floats2half2_rn(acc[mt][nt][0], acc[mt][nt][1]);
            __half2 hi = __floats2half2_rn(acc[mt][nt][2], acc[mt][nt][3]);
            *(__half2*)&Cs[r0 * SC + c0]       = lo;
            *(__half2*)&Cs[(r0 + 8) * SC + c0] = hi;
        }
    __syncthreads();

    __half* base = g_pri + (size_t)tg * 64 * 512 + half * 256;
    #pragma unroll
    for (int i = tid; i < 2048; i += 512) {
        int bb = i >> 5, off = i & 31;
        *reinterpret_cast<uint4*>(base + bb * 512 + off * 8) =
            *(const uint4*)&Cs[bb * SC + off * 8];
    }
}

// ---------------------------------------------------------------------------
// Kernel 2: fused dynamic routing, beta-free + 2-way t-interleave.
// Logits are linear in pri: b_t = (v1+...+vk).p_t -> only V[16] kept.
// Raw uint4 pri regs, lazy unpack. ~60 regs -> 2 CTAs/SM, MLP=2 in t-loop.
// ---------------------------------------------------------------------------
__device__ __forceinline__ void ld_raw(int tglob, int b, int lane,
                                       uint4& ua, uint4& ub) {
    const __half* pp = g_pri + (((size_t)(tglob * 64 + b)) << 9) + (lane << 4);
    ua = __ldg((const uint4*)pp);
    ub = __ldg((const uint4*)(pp + 8));
}

__device__ __forceinline__ float dot_raw(const float* v, uint4 ua, uint4 ub) {
    const __half2* ha = reinterpret_cast<const __half2*>(&ua);
    const __half2* hb = reinterpret_cast<const __half2*>(&ub);
    float s0 = 0.f, s1 = 0.f, s2 = 0.f, s3 = 0.f;
    #pragma unroll
    for (int k = 0; k < 4; k++) {
        float2 fa = __half22float2(ha[k]);
        float2 fb = __half22float2(hb[k]);
        s0 = fmaf(v[2 * k],         fa.x, s0);
        s1 = fmaf(v[2 * k + 1],     fa.y, s1);
        s2 = fmaf(v[8 + 2 * k],     fb.x, s2);
        s3 = fmaf(v[8 + 2 * k + 1], fb.y, s3);
    }
    return (s0 + s1) + (s2 + s3);
}

__device__ __forceinline__ void s_upd(float* s, float r, uint4 ua, uint4 ub) {
    const __half2* ha = reinterpret_cast<const __half2*>(&ua);
    const __half2* hb = reinterpret_cast<const __half2*>(&ub);
    #pragma unroll
    for (int k = 0; k < 4; k++) {
        float2 fa = __half22float2(ha[k]);
        float2 fb = __half22float2(hb[k]);
        s[2 * k]         = fmaf(r, fa.x, s[2 * k]);
        s[2 * k + 1]     = fmaf(r, fa.y, s[2 * k + 1]);
        s[8 + 2 * k]     = fmaf(r, fb.x, s[8 + 2 * k]);
        s[8 + 2 * k + 1] = fmaf(r, fb.y, s[8 + 2 * k + 1]);
    }
}

template<int NT>
__device__ __forceinline__ void route_body(int b, int t0, float* __restrict__ outm,
                                           float (*red)[512], float* vsm)
{
    int tid  = threadIdx.x;
    int w    = tid >> 5;
    int lane = tid & 31;

    float V[16];   // accumulated v1 + ... + vk

    // ---- pass 0: v1 = tanh(sum_t pri / 32) (softmax(0) uniform) ----
    {
        float s[16];
        #pragma unroll
        for (int d = 0; d < 16; d++) s[d] = 0.f;
        #pragma unroll 1
        for (int i = 0; i < NT; i += 2) {
            uint4 ua0, ub0, ua1, ub1;
            ld_raw(t0 + w + (i << 4),       b, lane, ua0, ub0);
            ld_raw(t0 + w + ((i + 1) << 4), b, lane, ua1, ub1);
            s_upd(s, 1.0f, ua0, ub0);
            s_upd(s, 1.0f, ua1, ub1);
        }
        #pragma unroll
        for (int d = 0; d < 16; d++) red[w][(lane << 4) + d] = s[d];
        __syncthreads();
        float tot = 0.f;
        #pragma unroll
        for (int ww = 0; ww < 16; ww++) tot += red[ww][tid];
        vsm[(tid >> 4) * 17 + (tid & 15)] = tanhf(tot * (1.0f / 32.0f));
        __syncthreads();
        #pragma unroll
        for (int d = 0; d < 16; d++) V[d] = vsm[lane * 17 + d];
        __syncthreads();
    }

    // ---- 3 routing iterations; logit recomputed as V.p each pass ----
    #pragma unroll 1
    for (int it = 0; it < 3; it++) {
        float s[16];
        #pragma unroll
        for (int d = 0; d < 16; d++) s[d] = 0.f;
        #pragma unroll 1
        for (int i = 0; i < NT; i += 2) {
            uint4 ua0, ub0, ua1, ub1;
            ld_raw(t0 + w + (i << 4),       b, lane, ua0, ub0);
            ld_raw(t0 + w + ((i + 1) << 4), b, lane, ua1, ub1);

            float b0 = dot_raw(V, ua0, ub0);
            float b1 = dot_raw(V, ua1, ub1);
            // softmax over 32 lanes (no max-subtract: |bt| small);
            // two independent butterfly chains pipeline across levels.
            float e0 = __expf(b0), e1 = __expf(b1);
            float Z0 = e0, Z1 = e1;
            #pragma unroll
            for (int off = 16; off > 0; off >>= 1) {
                Z0 += __shfl_xor_sync(0xffffffffu, Z0, off);
                Z1 += __shfl_xor_sync(0xffffffffu, Z1, off);
            }
            s_upd(s, __fdividef(e0, Z0), ua0, ub0);
            s_upd(s, __fdividef(e1, Z1), ua1, ub1);
        }
        #pragma unroll
        for (int d = 0; d < 16; d++) red[w][(lane << 4) + d] = s[d];
        __syncthreads();
        float tot = 0.f;
        #pragma unroll
        for (int ww = 0; ww < 16; ww++) tot += red[ww][tid];
        if (it == 2) {
            outm[(b << 9) + tid] = tanhf(tot);
        } else {
            vsm[(tid >> 4) * 17 + (tid & 15)] = tanhf(tot);
            __syncthreads();
            #pragma unroll
            for (int d = 0; d < 16; d++) V[d] += vsm[lane * 17 + d];
            __syncthreads();
        }
    }
}

__global__ __launch_bounds__(512, 2) void k_route(float* __restrict__ out)
{
    __shared__ float red[16][512];
    __shared__ float vsm[32 * 17];
    int m = blockIdx.x >> 6;
    int b = blockIdx.x & 63;
    if      (m == 0) route_body<8 >(b,   0, out,          red, vsm);
    else if (m == 1) route_body<32>(b, 128, out + 32768,  red, vsm);
    else if (m == 2) route_body<16>(b, 640, out + 65536,  red, vsm);
    else             route_body<16>(b, 896, out + 98304,  red, vsm);
}

extern "C" void kernel_launch(void* const* d_in, const int* in_sizes, int n_in,
                              void* d_out, int out_size)
{
    const float* xT = (const float*)d_in[0];
    const float* xA = (const float*)d_in[1];
    const float* xV = (const float*)d_in[2];
    const float* xF = (const float*)d_in[3];
    const float* wT = (const float*)d_in[4];
    const float* wA = (const float*)d_in[5];
    const float* wV = (const float*)d_in[6];
    const float* wF = (const float*)d_in[7];

    // Unconditional (no static guard): idempotent, allocation-free, immediate.
    cudaFuncSetAttribute(k_pri, cudaFuncAttributeMaxDynamicSharedMemorySize,
                         K_PRI_SMEM);

    k_pri  <<<2304, 512, K_PRI_SMEM>>>(xT, xA, xV, xF, wT, wA, wV, wF);
    k_route<<<256, 512>>>((float*)d_out);
}

// round 15
// speedup vs baseline: 1.1182x; 1.1182x over previous
#include <cuda_runtime.h>
#include <cuda_fp16.h>
#include <cuda_bf16.h>

// pri scratch: [t_global (1152)][b (64)][n*16+d (512)] fp16 = 75.5 MB
static __device__ __half g_pri[37748736];

// ---------------------------------------------------------------------------
// Kernel 1: pri = x_t @ W_t via single-pass tf32 MMA (m16n8k8, RNA-rounded).
// CTA = (t, nd-half). smem: Ws [256 x 68 f32] + Xs [64 x 68 f32] = 87KB
// -> 2 CTAs/SM. Stride 68 words => frag loads hit banks (4g+tq): conflict-free.
// ---------------------------------------------------------------------------
#define WS_WORDS (256 * 68)
#define XS_OFF   (WS_WORDS * 4)              // byte offset of Xs
#define K_PRI_SMEM (WS_WORDS * 4 + 64 * 68 * 4)   // 87040
#define SC 264                                // Cs fp16 row stride (reuses Ws)

__device__ __forceinline__ unsigned to_tf32(float x) {
    unsigned r;
    asm("cvt.rna.tf32.f32 %0, %1;" : "=r"(r) : "f"(x));
    return r;
}

__device__ __forceinline__ void mma_tf32(float* c, const unsigned* a,
                                         unsigned b0, unsigned b1) {
    asm volatile(
        "mma.sync.aligned.m16n8k8.row.col.f32.tf32.tf32.f32 "
        "{%0,%1,%2,%3}, {%4,%5,%6,%7}, {%8,%9}, {%0,%1,%2,%3};"
        : "+f"(c[0]), "+f"(c[1]), "+f"(c[2]), "+f"(c[3])
        : "r"(a[0]), "r"(a[1]), "r"(a[2]), "r"(a[3]), "r"(b0), "r"(b1));
}

__global__ __launch_bounds__(512, 2) void k_pri(
    const float* __restrict__ xT, const float* __restrict__ xA,
    const float* __restrict__ xV, const float* __restrict__ xF,
    const float* __restrict__ wT, const float* __restrict__ wA,
    const float* __restrict__ wV, const float* __restrict__ wF)
{
    extern __shared__ char smc[];
    unsigned* Ws = reinterpret_cast<unsigned*>(smc);            // [nd=256][j] tf32
    unsigned* Xs = reinterpret_cast<unsigned*>(smc + XS_OFF);   // [b=64][j]  tf32
    __half*   Cs = reinterpret_cast<__half*>(smc);              // reused after MMA

    int bid  = blockIdx.x;
    int tg   = bid >> 1;
    int half = bid & 1;
    const float* x; const float* w; int T, t;
    if (tg < 128)      { x = xT; w = wT; T = 128; t = tg;       }
    else if (tg < 640) { x = xA; w = wA; T = 512; t = tg - 128; }
    else if (tg < 896) { x = xV; w = wV; T = 256; t = tg - 640; }
    else               { x = xF; w = wF; T = 256; t = tg - 896; }

    int tid = threadIdx.x;

    // ---- stage x_t -> Xs (tf32, RNA) ----
    #pragma unroll
    for (int u = tid; u < 2048; u += 512) {
        int bb = u >> 5, jp = u & 31;
        float2 v2 = *reinterpret_cast<const float2*>(
            x + ((size_t)bb * T + t) * 64 + jp * 2);
        uint2 st; st.x = to_tf32(v2.x); st.y = to_tf32(v2.y);
        *reinterpret_cast<uint2*>(&Xs[bb * 68 + jp * 2]) = st;
    }

    // ---- stage this CTA's half of W_t -> Ws (tf32, RNA) ----
    const float4* w4 = reinterpret_cast<const float4*>(w + (size_t)t * 32768);
    #pragma unroll
    for (int u = tid; u < 2048; u += 512) {
        int d0c = u & 3;            // d-quad
        int jp  = (u >> 2) & 31;    // j-pair
        int nl  = u >> 7;           // local n 0..15
        int nbase = (half * 16 + nl) * 256 + jp * 8 + d0c;
        float4 va = __ldg(w4 + nbase);        // j = 2jp
        float4 vb = __ldg(w4 + nbase + 4);    // j = 2jp+1
        float aa[4] = {va.x, va.y, va.z, va.w};
        float bb4[4] = {vb.x, vb.y, vb.z, vb.w};
        #pragma unroll
        for (int q = 0; q < 4; q++) {
            int row = (nl << 4) + d0c * 4 + q;      // local nd 0..255
            uint2 st; st.x = to_tf32(aa[q]); st.y = to_tf32(bb4[q]);
            *reinterpret_cast<uint2*>(&Ws[row * 68 + jp * 2]) = st;
        }
    }
    __syncthreads();

    // ---- MMA: warp = (b-half 32) x (32-nd group); 8 k-steps of 8 ----
    int lane = tid & 31, wrp = tid >> 5;
    int g  = lane >> 2;
    int tq = lane & 3;
    int mbase  = (wrp & 1) * 32;       // b
    int ndbase = (wrp >> 1) * 32;      // local nd

    float acc[2][4][4];
    #pragma unroll
    for (int mt = 0; mt < 2; mt++)
        #pragma unroll
        for (int nt = 0; nt < 4; nt++)
            #pragma unroll
            for (int q = 0; q < 4; q++) acc[mt][nt][q] = 0.f;

    #pragma unroll
    for (int k0 = 0; k0 < 64; k0 += 8) {
        unsigned a[2][4];
        #pragma unroll
        for (int mt = 0; mt < 2; mt++) {
            int r0 = mbase + mt * 16 + g;
            int kc = k0 + tq;
            a[mt][0] = Xs[r0 * 68 + kc];
            a[mt][1] = Xs[(r0 + 8) * 68 + kc];
            a[mt][2] = Xs[r0 * 68 + kc + 4];
            a[mt][3] = Xs[(r0 + 8) * 68 + kc + 4];
        }
        #pragma unroll
        for (int nt = 0; nt < 4; nt++) {
            int col = ndbase + nt * 8 + g;
            int kc  = k0 + tq;
            unsigned b0 = Ws[col * 68 + kc];
            unsigned b1 = Ws[col * 68 + kc + 4];
            #pragma unroll
            for (int mt = 0; mt < 2; mt++)
                mma_tf32(acc[mt][nt], a[mt], b0, b1);
        }
    }
    __syncthreads();   // Ws no longer needed; reuse as Cs

    #pragma unroll
    for (int mt = 0; mt < 2; mt++)
        #pragma unroll
        for (int nt = 0; nt < 4; nt++) {
            int r0 = mbase + mt * 16 + g;            // b
            int c0 = ndbase + nt * 8 + tq * 2;       // local nd
            __half2 lo = __floats2half2_rn(acc[mt][nt][0], acc[mt][nt][1]);
            __half2 hi = __floats2half2_rn(acc[mt][nt][2], acc[mt][nt][3]);
            *(__half2*)&Cs[r0 * SC + c0]       = lo;
            *(__half2*)&Cs[(r0 + 8) * SC + c0] = hi;
        }
    __syncthreads();

    __half* base = g_pri + (size_t)tg * 64 * 512 + half * 256;
    #pragma unroll
    for (int i = tid; i < 2048; i += 512) {
        int bb = i >> 5, off = i & 31;
        *reinterpret_cast<uint4*>(base + bb * 512 + off * 8) =
            *(const uint4*)&Cs[bb * SC + off * 8];
    }
}

// ---------------------------------------------------------------------------
// Kernel 2: fused dynamic routing (best-measured R5 variant, 53.95us).
// ---------------------------------------------------------------------------
__device__ __forceinline__ void h8f(uint4 u, float* pf) {
    __half2* h = reinterpret_cast<__half2*>(&u);
    #pragma unroll
    for (int k = 0; k < 4; k++) {
        float2 f = __half22float2(h[k]);
        pf[2 * k] = f.x; pf[2 * k + 1] = f.y;
    }
}

__device__ __forceinline__ void load_pf(int tglob, int b, int lane, float* pf) {
    const __half* pp = g_pri + (((size_t)(tglob * 64 + b)) << 9) + (lane << 4);
    uint4 u0 = __ldg((const uint4*)pp);
    uint4 u1 = __ldg((const uint4*)(pp + 8));
    h8f(u0, pf); h8f(u1, pf + 8);
}

__device__ __forceinline__ float dot16(const float* v, const float* p) {
    float s0 = 0.f, s1 = 0.f, s2 = 0.f, s3 = 0.f;
    #pragma unroll
    for (int d = 0; d < 4; d++) {
        s0 = fmaf(v[d],      p[d],      s0);
        s1 = fmaf(v[d + 4],  p[d + 4],  s1);
        s2 = fmaf(v[d + 8],  p[d + 8],  s2);
        s3 = fmaf(v[d + 12], p[d + 12], s3);
    }
    return (s0 + s1) + (s2 + s3);
}

template<int NT>
__device__ __forceinline__ void route_body(int b, int t0, float* __restrict__ outm,
                                           float (*red)[512], float* vsm)
{
    int tid  = threadIdx.x;
    int w    = tid >> 5;
    int lane = tid & 31;

    float beta[NT];
    #pragma unroll
    for (int i = 0; i < NT; i++) beta[i] = 0.f;
    float v[16];

    {
        float s[16];
        #pragma unroll
        for (int d = 0; d < 16; d++) s[d] = 0.f;
        #pragma unroll
        for (int i = 0; i < NT; i += 2) {
            float pa[16], pb[16];
            load_pf(t0 + w + (i << 4), b, lane, pa);
            load_pf(t0 + w + ((i + 1) << 4), b, lane, pb);
            #pragma unroll
            for (int d = 0; d < 16; d++) s[d] += pa[d] + pb[d];
        }
        #pragma unroll
        for (int d = 0; d < 16; d++) red[w][(lane << 4) + d] = s[d];
        __syncthreads();
        float tot = 0.f;
        #pragma unroll
        for (int ww = 0; ww < 16; ww++) tot += red[ww][tid];
        vsm[(tid >> 4) * 17 + (tid & 15)] = tanhf(tot * (1.0f / 32.0f));
        __syncthreads();
        #pragma unroll
        for (int d = 0; d < 16; d++) v[d] = vsm[lane * 17 + d];
        __syncthreads();
    }

    #pragma unroll 1
    for (int it = 0; it < 3; it++) {
        float s[16];
        #pragma unroll
        for (int d = 0; d < 16; d++) s[d] = 0.f;
        #pragma unroll
        for (int i = 0; i < NT; i += 2) {
            float pa[16], pb[16];
            load_pf(t0 + w + (i << 4), b, lane, pa);
            load_pf(t0 + w + ((i + 1) << 4), b, lane, pb);

            float ba = beta[i]     + dot16(v, pa);
            float bb = beta[i + 1] + dot16(v, pb);
            beta[i] = ba; beta[i + 1] = bb;

            float ea = __expf(ba), eb = __expf(bb);
            float Za = ea, Zb = eb;
            #pragma unroll
            for (int off = 16; off > 0; off >>= 1) {
                Za += __shfl_xor_sync(0xffffffffu, Za, off);
                Zb += __shfl_xor_sync(0xffffffffu, Zb, off);
            }
            float ra = __fdividef(ea, Za);
            float rb = __fdividef(eb, Zb);
            #pragma unroll
            for (int d = 0; d < 16; d++)
                s[d] = fmaf(ra, pa[d], fmaf(rb, pb[d], s[d]));
        }
        #pragma unroll
        for (int d = 0; d < 16; d++) red[w][(lane << 4) + d] = s[d];
        __syncthreads();
        float tot = 0.f;
        #pragma unroll
        for (int ww = 0; ww < 16; ww++) tot += red[ww][tid];
        if (it == 2) {
            outm[(b << 9) + tid] = tanhf(tot);
        } else {
            vsm[(tid >> 4) * 17 + (tid & 15)] = tanhf(tot);
            __syncthreads();
            #pragma unroll
            for (int d = 0; d < 16; d++) v[d] = vsm[lane * 17 + d];
            __syncthreads();
        }
    }
}

__global__ __launch_bounds__(512) void k_route(float* __restrict__ out)
{
    __shared__ float red[16][512];
    __shared__ float vsm[32 * 17];
    int m = blockIdx.x >> 6;
    int b = blockIdx.x & 63;
    if      (m == 0) route_body<8 >(b,   0, out,          red, vsm);
    else if (m == 1) route_body<32>(b, 128, out + 32768,  red, vsm);
    else if (m == 2) route_body<16>(b, 640, out + 65536,  red, vsm);
    else             route_body<16>(b, 896, out + 98304,  red, vsm);
}

extern "C" void kernel_launch(void* const* d_in, const int* in_sizes, int n_in,
                              void* d_out, int out_size)
{
    const float* xT = (const float*)d_in[0];
    const float* xA = (const float*)d_in[1];
    const float* xV = (const float*)d_in[2];
    const float* xF = (const float*)d_in[3];
    const float* wT = (const float*)d_in[4];
    const float* wA = (const float*)d_in[5];
    const float* wV = (const float*)d_in[6];
    const float* wF = (const float*)d_in[7];

    // Unconditional (no static guard): idempotent, allocation-free, immediate.
    cudaFuncSetAttribute(k_pri, cudaFuncAttributeMaxDynamicSharedMemorySize,
                         K_PRI_SMEM);

    k_pri  <<<2304, 512, K_PRI_SMEM>>>(xT, xA, xV, xF, wT, wA, wV, wF);
    k_route<<<256, 512>>>((float*)d_out);
}